// round 3
// baseline (speedup 1.0000x reference)
#include <cuda_runtime.h>
#include <cstdint>
#include <cstddef>

#define ND 4
#define NB 128
#define NL 200
#define DIM 512
#define M_TOTAL (ND * NB * NL)   // 102400
#define LN_EPS 1e-8f

#define BM 64
#define BN 128
#define BK 16
#define NKT (DIM / BK)           // 32

// -------- device scratch (static, allocation-guard-safe) --------
__device__ int g_count[ND];
__device__ int g_list[ND][M_TOTAL];

// -------- packed f32x2 helpers --------
#define FMA2(d, a, b) \
    asm("fma.rn.f32x2 %0, %1, %2, %0;" : "+l"(d) : "l"(a), "l"(b))
#define PACKB(d, f) \
    asm("mov.b64 %0, {%1, %1};" : "=l"(d) : "f"(f))

__device__ __forceinline__ float f2lo(unsigned long long v) {
    return __uint_as_float((unsigned)(v & 0xffffffffULL));
}
__device__ __forceinline__ float f2hi(unsigned long long v) {
    return __uint_as_float((unsigned)(v >> 32));
}

// ================= kernel 0: reset counters =================
__global__ void reset_kernel() {
    if (threadIdx.x < ND) g_count[threadIdx.x] = 0;
}

// ================= kernel 1: routing / compaction =================
__global__ void route_kernel(const int* __restrict__ lg_dom) {
    int m = blockIdx.x * blockDim.x + threadIdx.x;
    if (m >= M_TOTAL) return;
    int i = m / (NB * NL);
    int r = m - i * (NB * NL);
    int b = r / NL;
    int l = r - b * NL;
    int lg = lg_dom[b * (ND * NL) + i * NL + l];
    if (lg > 0) {
        int e = lg - 1;
        int slot = atomicAdd(&g_count[e], 1);
        g_list[e][slot] = m;
    }
}

// ================= kernel 2: grouped SGEMM (gathered rows) =================
// Y[m, :] = X[m, :] @ W[e]^T + bias[e]  for m in g_list[e]
// Tile: 64 tokens x 128 outs, K-chunk 16, 256 threads, microtile 4x8,
// f32x2 packed accumulation (pairs along the output dimension).
__global__ void __launch_bounds__(256, 2)
gemm_kernel(const float* __restrict__ X, const float* __restrict__ W,
            const float* __restrict__ Bias, float* __restrict__ Y)
{
    const int e   = blockIdx.z;
    const int cnt = g_count[e];
    const int m0  = blockIdx.x * BM;
    if (m0 >= cnt) return;
    const int n0 = blockIdx.y * BN;
    const int* __restrict__ list = g_list[e];
    const float* __restrict__ Wb = W + (size_t)e * DIM * DIM;

    __shared__ float As[2][BK][BM];
    __shared__ float Bs[2][BK][BN];

    const int tid = threadIdx.x;

    // A loader: one float4 (4 k) per thread, gathered token rows
    const int a_t  = tid >> 2;            // 0..63
    const int a_kg = (tid & 3) * 4;       // 0,4,8,12
    const float* a_src = nullptr;
    if (m0 + a_t < cnt) {
        int am = list[m0 + a_t];
        a_src = X + (size_t)am * DIM + a_kg;
    }
    // B loader: two float4 (8 k) per thread
    const int b_o  = tid >> 1;            // 0..127
    const int b_kg = (tid & 1) * 8;       // 0,8
    const float* b_src = Wb + (size_t)(n0 + b_o) * DIM + b_kg;

    // compute mapping: microtile 4 tokens x 8 outputs
    const int ty = tid >> 4;              // 0..15
    const int tx = tid & 15;              // 0..15
    const int t0 = ty * 4;
    const int o0 = tx * 8;

    unsigned long long acc[16];
#pragma unroll
    for (int q = 0; q < 16; ++q) acc[q] = 0ULL;

    float4 ar  = a_src ? *(const float4*)a_src : make_float4(0.f, 0.f, 0.f, 0.f);
    float4 br0 = *(const float4*)(b_src);
    float4 br1 = *(const float4*)(b_src + 4);

    // stage tile 0
    As[0][a_kg + 0][a_t] = ar.x;
    As[0][a_kg + 1][a_t] = ar.y;
    As[0][a_kg + 2][a_t] = ar.z;
    As[0][a_kg + 3][a_t] = ar.w;
    Bs[0][b_kg + 0][b_o] = br0.x;
    Bs[0][b_kg + 1][b_o] = br0.y;
    Bs[0][b_kg + 2][b_o] = br0.z;
    Bs[0][b_kg + 3][b_o] = br0.w;
    Bs[0][b_kg + 4][b_o] = br1.x;
    Bs[0][b_kg + 5][b_o] = br1.y;
    Bs[0][b_kg + 6][b_o] = br1.z;
    Bs[0][b_kg + 7][b_o] = br1.w;
    __syncthreads();

    int buf = 0;
    for (int kt = 0; kt < NKT; ++kt) {
        const bool has_next = (kt + 1 < NKT);
        if (has_next) {
            const int k0 = (kt + 1) * BK;
            ar  = a_src ? *(const float4*)(a_src + k0) : make_float4(0.f, 0.f, 0.f, 0.f);
            br0 = *(const float4*)(b_src + k0);
            br1 = *(const float4*)(b_src + k0 + 4);
        }
#pragma unroll
        for (int kk = 0; kk < BK; ++kk) {
            float4 av = *(const float4*)(&As[buf][kk][t0]);
            ulonglong2 bb0 = *(const ulonglong2*)(&Bs[buf][kk][o0]);
            ulonglong2 bb1 = *(const ulonglong2*)(&Bs[buf][kk][o0 + 4]);
            unsigned long long a2[4], b2[4];
            PACKB(a2[0], av.x);
            PACKB(a2[1], av.y);
            PACKB(a2[2], av.z);
            PACKB(a2[3], av.w);
            b2[0] = bb0.x; b2[1] = bb0.y; b2[2] = bb1.x; b2[3] = bb1.y;
#pragma unroll
            for (int t = 0; t < 4; ++t) {
#pragma unroll
                for (int o = 0; o < 4; ++o) {
                    FMA2(acc[t * 4 + o], a2[t], b2[o]);
                }
            }
        }
        if (has_next) {
            const int nb = buf ^ 1;
            As[nb][a_kg + 0][a_t] = ar.x;
            As[nb][a_kg + 1][a_t] = ar.y;
            As[nb][a_kg + 2][a_t] = ar.z;
            As[nb][a_kg + 3][a_t] = ar.w;
            Bs[nb][b_kg + 0][b_o] = br0.x;
            Bs[nb][b_kg + 1][b_o] = br0.y;
            Bs[nb][b_kg + 2][b_o] = br0.z;
            Bs[nb][b_kg + 3][b_o] = br0.w;
            Bs[nb][b_kg + 4][b_o] = br1.x;
            Bs[nb][b_kg + 5][b_o] = br1.y;
            Bs[nb][b_kg + 6][b_o] = br1.z;
            Bs[nb][b_kg + 7][b_o] = br1.w;
            __syncthreads();
            buf = nb;
        }
    }

    // epilogue: add bias, scatter to output rows
    float bias[8];
    {
        float4 bv0 = *(const float4*)(Bias + e * DIM + n0 + o0);
        float4 bv1 = *(const float4*)(Bias + e * DIM + n0 + o0 + 4);
        bias[0] = bv0.x; bias[1] = bv0.y; bias[2] = bv0.z; bias[3] = bv0.w;
        bias[4] = bv1.x; bias[5] = bv1.y; bias[6] = bv1.z; bias[7] = bv1.w;
    }
#pragma unroll
    for (int t = 0; t < 4; ++t) {
        int mi = m0 + t0 + t;
        if (mi >= cnt) continue;
        int m = list[mi];
        float* dst = Y + (size_t)m * DIM + n0 + o0;
        float4 v0, v1;
        v0.x = f2lo(acc[t * 4 + 0]) + bias[0];
        v0.y = f2hi(acc[t * 4 + 0]) + bias[1];
        v0.z = f2lo(acc[t * 4 + 1]) + bias[2];
        v0.w = f2hi(acc[t * 4 + 1]) + bias[3];
        v1.x = f2lo(acc[t * 4 + 2]) + bias[4];
        v1.y = f2hi(acc[t * 4 + 2]) + bias[5];
        v1.z = f2lo(acc[t * 4 + 3]) + bias[6];
        v1.w = f2hi(acc[t * 4 + 3]) + bias[7];
        *(float4*)(dst)     = v0;
        *(float4*)(dst + 4) = v1;
    }
}

// ================= kernel 3: LayerNorm + pos/neg logits =================
__device__ __forceinline__ float2 blockRed2(float a, float b, float2* buf,
                                            int lane, int wid) {
#pragma unroll
    for (int o = 16; o > 0; o >>= 1) {
        a += __shfl_xor_sync(0xffffffffu, a, o);
        b += __shfl_xor_sync(0xffffffffu, b, o);
    }
    if (lane == 0) buf[wid] = make_float2(a, b);
    __syncthreads();
    float2 r;
    r.x = buf[0].x + buf[1].x + buf[2].x + buf[3].x;
    r.y = buf[0].y + buf[1].y + buf[2].y + buf[3].y;
    __syncthreads();  // allow buffer reuse
    return r;
}

__global__ void __launch_bounds__(128)
ln_logits_kernel(float* __restrict__ Ybuf,
                 float* __restrict__ pos_out, float* __restrict__ neg_out,
                 const float* __restrict__ emb,
                 const float* __restrict__ gamma, const float* __restrict__ beta,
                 const int* __restrict__ lg_dom,
                 const int* __restrict__ pos_idx, const int* __restrict__ neg_idx)
{
    const int m = blockIdx.x;
    const int i = m / (NB * NL);
    const int r = m - i * (NB * NL);
    const int b = r / NL;
    const int l = r - b * NL;
    const int gidx = b * (ND * NL) + i * NL + l;

    const int tid  = threadIdx.x;
    const int lane = tid & 31;
    const int wid  = tid >> 5;

    __shared__ float2 red[4];

    const int lg = lg_dom[gidx];
    float4 x;
    if (lg > 0) {
        x = ((const float4*)(Ybuf + (size_t)m * DIM))[tid];
    } else {
        x = make_float4(0.f, 0.f, 0.f, 0.f);
    }

    // pass 1: mean
    float s = x.x + x.y + x.z + x.w;
    float2 r1 = blockRed2(s, 0.f, red, lane, wid);
    const float mu = r1.x * (1.0f / DIM);

    // pass 2: variance (two-pass, matches reference numerics)
    float dx0 = x.x - mu, dx1 = x.y - mu, dx2 = x.z - mu, dx3 = x.w - mu;
    float ss = dx0 * dx0 + dx1 * dx1 + dx2 * dx2 + dx3 * dx3;
    float2 r2 = blockRed2(ss, 0.f, red, lane, wid);
    const float var = r2.x * (1.0f / DIM);
    const float rstd = rsqrtf(var + LN_EPS);

    float4 g  = ((const float4*)gamma)[tid];
    float4 be = ((const float4*)beta)[tid];
    float4 y;
    y.x = dx0 * rstd * g.x + be.x;
    y.y = dx1 * rstd * g.y + be.y;
    y.z = dx2 * rstd * g.z + be.z;
    y.w = dx3 * rstd * g.w + be.w;
    ((float4*)(Ybuf + (size_t)m * DIM))[tid] = y;

    // logits: dot with gathered pos/neg embedding rows
    const float* pe = emb + (size_t)pos_idx[gidx] * DIM;
    const float* ne = emb + (size_t)neg_idx[gidx] * DIM;
    float4 p = ((const float4*)pe)[tid];
    float4 n = ((const float4*)ne)[tid];
    float dp = y.x * p.x + y.y * p.y + y.z * p.z + y.w * p.w;
    float dn = y.x * n.x + y.y * n.y + y.z * n.z + y.w * n.w;
    float2 r3 = blockRed2(dp, dn, red, lane, wid);
    if (tid == 0) {
        pos_out[m] = r3.x;
        neg_out[m] = r3.y;
    }
}

// ================= launch =================
extern "C" void kernel_launch(void* const* d_in, const int* in_sizes, int n_in,
                              void* d_out, int out_size) {
    const float* X     = (const float*)d_in[0];   // log_feats [4,128,200,512]
    const float* Wm    = (const float*)d_in[1];   // W_maps [4,512,512]
    const float* bm    = (const float*)d_in[2];   // b_maps [4,512]
    const float* emb   = (const float*)d_in[3];   // emb_table [100002,512]
    const float* gamma = (const float*)d_in[4];   // [512]
    const float* beta  = (const float*)d_in[5];   // [512]
    const int*   lg    = (const int*)d_in[6];     // lg_dom [128,4,200]
    const int*   pos   = (const int*)d_in[7];     // pos_oth_dom [128,4,200]
    const int*   neg   = (const int*)d_in[8];     // neg_oth_dom [128,4,200]

    float* out     = (float*)d_out;
    float* mapped  = out;                                  // [4,128,200,512]
    float* pos_out = out + (size_t)M_TOTAL * DIM;          // [4,128,200]
    float* neg_out = pos_out + M_TOTAL;                    // [4,128,200]

    reset_kernel<<<1, 32>>>();
    route_kernel<<<(M_TOTAL + 255) / 256, 256>>>(lg);

    dim3 grid((M_TOTAL + BM - 1) / BM, DIM / BN, ND);
    gemm_kernel<<<grid, 256>>>(X, Wm, bm, mapped);

    ln_logits_kernel<<<M_TOTAL, 128>>>(mapped, pos_out, neg_out,
                                       emb, gamma, beta, lg, pos, neg);
}

// round 4
// speedup vs baseline: 3.1543x; 3.1543x over previous
#include <cuda_runtime.h>
#include <cstdint>
#include <cstddef>

#define ND 4
#define NB 128
#define NL 200
#define DIM 512
#define M_TOTAL (ND * NB * NL)   // 102400
#define LN_EPS 1e-8f

// GEMM tiling (tensor-core path)
#define BM 128
#define BN 128
#define BK 32
#define KSTEPS (BK / 8)          // 4 mma k-steps per tile
#define NKT (DIM / BK)           // 16 k-iterations
#define LDS_K (BK + 4)           // 36: padded row stride, conflict-free fragments
#define SMEM_WORDS (2 * BM * LDS_K)          // per matrix (2 stages)
#define SMEM_BYTES (2 * SMEM_WORDS * 4)      // A + B total = 73728 B

// -------- device scratch (static, allocation-guard-safe) --------
__device__ int g_count[ND];
__device__ int g_list[ND][M_TOTAL];

// -------- tf32 helpers --------
__device__ __forceinline__ unsigned f2tf(float f) {
    unsigned u;
    asm("cvt.rna.tf32.f32 %0, %1;" : "=r"(u) : "f"(f));
    return u;
}

__device__ __forceinline__ void mma_tf32(float* d, const unsigned* a, const unsigned* b) {
    asm("mma.sync.aligned.m16n8k8.row.col.f32.tf32.tf32.f32 "
        "{%0,%1,%2,%3}, {%4,%5,%6,%7}, {%8,%9}, {%0,%1,%2,%3};"
        : "+f"(d[0]), "+f"(d[1]), "+f"(d[2]), "+f"(d[3])
        : "r"(a[0]), "r"(a[1]), "r"(a[2]), "r"(a[3]),
          "r"(b[0]), "r"(b[1]));
}

// ================= kernel 0: reset counters =================
__global__ void reset_kernel() {
    if (threadIdx.x < ND) g_count[threadIdx.x] = 0;
}

// ================= kernel 1: routing / compaction =================
__global__ void route_kernel(const int* __restrict__ lg_dom) {
    int m = blockIdx.x * blockDim.x + threadIdx.x;
    if (m >= M_TOTAL) return;
    int i = m / (NB * NL);
    int r = m - i * (NB * NL);
    int b = r / NL;
    int l = r - b * NL;
    int lg = lg_dom[b * (ND * NL) + i * NL + l];
    if (lg > 0) {
        int e = lg - 1;
        int slot = atomicAdd(&g_count[e], 1);
        g_list[e][slot] = m;
    }
}

// ================= kernel 2: grouped TF32 tensor-core GEMM =================
// Y[m, :] = X[m, :] @ W[e]^T + bias[e]  for m in g_list[e]
// 128x128x32 tile, 256 threads (8 warps 4Mx2N), warp tile 32x64,
// mma.sync m16n8k8 tf32, double-buffered smem, cvt.rna at staging.
__global__ void __launch_bounds__(256)
gemm_tc_kernel(const float* __restrict__ X, const float* __restrict__ W,
               const float* __restrict__ Bias, float* __restrict__ Y)
{
    const int e   = blockIdx.z;
    const int cnt = g_count[e];
    const int m0  = blockIdx.x * BM;
    if (m0 >= cnt) return;
    const int n0 = blockIdx.y * BN;
    const int* __restrict__ list = g_list[e];
    const float* __restrict__ Wb = W + (size_t)e * DIM * DIM;

    extern __shared__ unsigned smem_u[];
    unsigned* As = smem_u;                // [2][BM][LDS_K]
    unsigned* Bs = smem_u + SMEM_WORDS;   // [2][BN][LDS_K]

    const int tid  = threadIdx.x;
    const int lane = tid & 31;
    const int wid  = tid >> 5;
    const int warp_m = wid & 3;           // 0..3 -> 32 rows each
    const int warp_n = wid >> 2;          // 0..1 -> 64 cols each
    const int gr = lane >> 2;             // 0..7
    const int tc = lane & 3;              // 0..3

    // ---- loaders: 2 threads per row, 16 floats (4 float4) each ----
    const int l_row  = tid >> 1;          // 0..127
    const int l_half = tid & 1;           // 0,1 -> k offset 0 / 16
    const bool a_valid = (m0 + l_row < cnt);
    const float* a_g = a_valid
        ? (X + (size_t)list[m0 + l_row] * DIM + l_half * 16) : nullptr;
    const float* b_g = Wb + (size_t)(n0 + l_row) * DIM + l_half * 16;

    float4 va[4], vb[4];

    auto ldg_tile = [&](int kt) {
        const int k0 = kt * BK;
        if (a_valid) {
#pragma unroll
            for (int j = 0; j < 4; ++j) va[j] = *(const float4*)(a_g + k0 + j * 4);
        } else {
#pragma unroll
            for (int j = 0; j < 4; ++j) va[j] = make_float4(0.f, 0.f, 0.f, 0.f);
        }
#pragma unroll
        for (int j = 0; j < 4; ++j) vb[j] = *(const float4*)(b_g + k0 + j * 4);
    };

    auto sts_tile = [&](int st) {
        unsigned* ap = As + (st * BM + l_row) * LDS_K + l_half * 16;
        unsigned* bp = Bs + (st * BN + l_row) * LDS_K + l_half * 16;
#pragma unroll
        for (int j = 0; j < 4; ++j) {
            uint4 ua = make_uint4(f2tf(va[j].x), f2tf(va[j].y), f2tf(va[j].z), f2tf(va[j].w));
            uint4 ub = make_uint4(f2tf(vb[j].x), f2tf(vb[j].y), f2tf(vb[j].z), f2tf(vb[j].w));
            *(uint4*)(ap + j * 4) = ua;
            *(uint4*)(bp + j * 4) = ub;
        }
    };

    float acc[2][8][4];
#pragma unroll
    for (int i = 0; i < 2; ++i)
#pragma unroll
        for (int j = 0; j < 8; ++j)
#pragma unroll
            for (int q = 0; q < 4; ++q) acc[i][j][q] = 0.f;

    // ---- prologue: tile 0 staged, tile 1 in regs ----
    ldg_tile(0);
    sts_tile(0);
    __syncthreads();
    ldg_tile(1);

    for (int kt = 0; kt < NKT; ++kt) {
        const int st = kt & 1;
#pragma unroll
        for (int ks = 0; ks < KSTEPS; ++ks) {
            const int k = ks * 8;
            unsigned afr[2][4], bfr[8][2];
#pragma unroll
            for (int i = 0; i < 2; ++i) {
                const unsigned* p = As + (st * BM + warp_m * 32 + i * 16 + gr) * LDS_K + k + tc;
                afr[i][0] = p[0];
                afr[i][1] = p[8 * LDS_K];
                afr[i][2] = p[4];
                afr[i][3] = p[8 * LDS_K + 4];
            }
#pragma unroll
            for (int j = 0; j < 8; ++j) {
                const unsigned* p = Bs + (st * BN + warp_n * 64 + j * 8 + gr) * LDS_K + k + tc;
                bfr[j][0] = p[0];
                bfr[j][1] = p[4];
            }
#pragma unroll
            for (int i = 0; i < 2; ++i)
#pragma unroll
                for (int j = 0; j < 8; ++j)
                    mma_tf32(acc[i][j], afr[i], bfr[j]);
        }
        if (kt + 1 < NKT) {
            __syncthreads();          // everyone done with stage st^1 from iter kt-1
            sts_tile(st ^ 1);         // stage tile kt+1
            if (kt + 2 < NKT) ldg_tile(kt + 2);
            __syncthreads();          // staged tile visible
        }
    }

    // ---- epilogue: bias add + scatter to gathered rows ----
#pragma unroll
    for (int i = 0; i < 2; ++i) {
        const int mr0 = m0 + warp_m * 32 + i * 16 + gr;
        const int mr1 = mr0 + 8;
        const bool v0 = (mr0 < cnt);
        const bool v1 = (mr1 < cnt);
        float* dst0 = v0 ? (Y + (size_t)list[mr0] * DIM + n0) : nullptr;
        float* dst1 = v1 ? (Y + (size_t)list[mr1] * DIM + n0) : nullptr;
#pragma unroll
        for (int j = 0; j < 8; ++j) {
            const int nf = warp_n * 64 + j * 8 + 2 * tc;
            float2 bv = *(const float2*)(Bias + e * DIM + n0 + nf);
            if (v0) {
                float2 o;
                o.x = acc[i][j][0] + bv.x;
                o.y = acc[i][j][1] + bv.y;
                *(float2*)(dst0 + nf) = o;
            }
            if (v1) {
                float2 o;
                o.x = acc[i][j][2] + bv.x;
                o.y = acc[i][j][3] + bv.y;
                *(float2*)(dst1 + nf) = o;
            }
        }
    }
}

// ================= kernel 3: LayerNorm + pos/neg logits =================
__device__ __forceinline__ float2 blockRed2(float a, float b, float2* buf,
                                            int lane, int wid) {
#pragma unroll
    for (int o = 16; o > 0; o >>= 1) {
        a += __shfl_xor_sync(0xffffffffu, a, o);
        b += __shfl_xor_sync(0xffffffffu, b, o);
    }
    if (lane == 0) buf[wid] = make_float2(a, b);
    __syncthreads();
    float2 r;
    r.x = buf[0].x + buf[1].x + buf[2].x + buf[3].x;
    r.y = buf[0].y + buf[1].y + buf[2].y + buf[3].y;
    __syncthreads();  // allow buffer reuse
    return r;
}

__global__ void __launch_bounds__(128)
ln_logits_kernel(float* __restrict__ Ybuf,
                 float* __restrict__ pos_out, float* __restrict__ neg_out,
                 const float* __restrict__ emb,
                 const float* __restrict__ gamma, const float* __restrict__ beta,
                 const int* __restrict__ lg_dom,
                 const int* __restrict__ pos_idx, const int* __restrict__ neg_idx)
{
    const int m = blockIdx.x;
    const int i = m / (NB * NL);
    const int r = m - i * (NB * NL);
    const int b = r / NL;
    const int l = r - b * NL;
    const int gidx = b * (ND * NL) + i * NL + l;

    const int tid  = threadIdx.x;
    const int lane = tid & 31;
    const int wid  = tid >> 5;

    __shared__ float2 red[4];

    const int lg = lg_dom[gidx];
    float4 x;
    if (lg > 0) {
        x = ((const float4*)(Ybuf + (size_t)m * DIM))[tid];
    } else {
        x = make_float4(0.f, 0.f, 0.f, 0.f);
    }

    // pass 1: mean
    float s = x.x + x.y + x.z + x.w;
    float2 r1 = blockRed2(s, 0.f, red, lane, wid);
    const float mu = r1.x * (1.0f / DIM);

    // pass 2: variance (two-pass, matches reference numerics)
    float dx0 = x.x - mu, dx1 = x.y - mu, dx2 = x.z - mu, dx3 = x.w - mu;
    float ss = dx0 * dx0 + dx1 * dx1 + dx2 * dx2 + dx3 * dx3;
    float2 r2 = blockRed2(ss, 0.f, red, lane, wid);
    const float var = r2.x * (1.0f / DIM);
    const float rstd = rsqrtf(var + LN_EPS);

    float4 g  = ((const float4*)gamma)[tid];
    float4 be = ((const float4*)beta)[tid];
    float4 y;
    y.x = dx0 * rstd * g.x + be.x;
    y.y = dx1 * rstd * g.y + be.y;
    y.z = dx2 * rstd * g.z + be.z;
    y.w = dx3 * rstd * g.w + be.w;
    ((float4*)(Ybuf + (size_t)m * DIM))[tid] = y;

    // logits: dot with gathered pos/neg embedding rows
    const float* pe = emb + (size_t)pos_idx[gidx] * DIM;
    const float* ne = emb + (size_t)neg_idx[gidx] * DIM;
    float4 p = ((const float4*)pe)[tid];
    float4 n = ((const float4*)ne)[tid];
    float dp = y.x * p.x + y.y * p.y + y.z * p.z + y.w * p.w;
    float dn = y.x * n.x + y.y * n.y + y.z * n.z + y.w * n.w;
    float2 r3 = blockRed2(dp, dn, red, lane, wid);
    if (tid == 0) {
        pos_out[m] = r3.x;
        neg_out[m] = r3.y;
    }
}

// ================= launch =================
extern "C" void kernel_launch(void* const* d_in, const int* in_sizes, int n_in,
                              void* d_out, int out_size) {
    const float* X     = (const float*)d_in[0];   // log_feats [4,128,200,512]
    const float* Wm    = (const float*)d_in[1];   // W_maps [4,512,512]
    const float* bm    = (const float*)d_in[2];   // b_maps [4,512]
    const float* emb   = (const float*)d_in[3];   // emb_table [100002,512]
    const float* gamma = (const float*)d_in[4];   // [512]
    const float* beta  = (const float*)d_in[5];   // [512]
    const int*   lg    = (const int*)d_in[6];     // lg_dom [128,4,200]
    const int*   pos   = (const int*)d_in[7];     // pos_oth_dom [128,4,200]
    const int*   neg   = (const int*)d_in[8];     // neg_oth_dom [128,4,200]

    float* out     = (float*)d_out;
    float* mapped  = out;                                  // [4,128,200,512]
    float* pos_out = out + (size_t)M_TOTAL * DIM;          // [4,128,200]
    float* neg_out = pos_out + M_TOTAL;                    // [4,128,200]

    static bool attr_set = false;
    if (!attr_set) {
        cudaFuncSetAttribute(gemm_tc_kernel,
                             cudaFuncAttributeMaxDynamicSharedMemorySize,
                             SMEM_BYTES);
        attr_set = true;
    }

    reset_kernel<<<1, 32>>>();
    route_kernel<<<(M_TOTAL + 255) / 256, 256>>>(lg);

    dim3 grid((M_TOTAL + BM - 1) / BM, DIM / BN, ND);
    gemm_tc_kernel<<<grid, 256, SMEM_BYTES>>>(X, Wm, bm, mapped);

    ln_logits_kernel<<<M_TOTAL, 128>>>(mapped, pos_out, neg_out,
                                       emb, gamma, beta, lg, pos, neg);
}